// round 16
// baseline (speedup 1.0000x reference)
#include <cuda_runtime.h>
#include <cmath>

#define NLV 16
#define TABLE_SIZE (1u << 19)
#define HMASK (TABLE_SIZE - 1u)
#define P1 2654435761u
#define P2 805459861u

#define NP_MAX 1000000
#define GRID_BITS 6
#define GRID_RES (1 << GRID_BITS)          // 64
#define NBINS (1 << (3 * GRID_BITS))       // 262144
#define SCAN_BLOCK 512
#define NSCAN_BLOCKS (NBINS / SCAN_BLOCK)  // 512

struct LvlParams { int r[NLV]; unsigned dy[NLV]; unsigned dz[NLV]; };

// ---- scratch (static device globals; no allocation) ----
__device__ unsigned g_hist[NBINS];
__device__ unsigned g_blocksums[NSCAN_BLOCKS];
__device__ unsigned g_ticket = 0;    // self-cleaning: last block resets to 0
__device__ float4   g_pts[NP_MAX];   // x,y,z, perm-as-bits

// ---------------- Morton ----------------
__device__ __forceinline__ unsigned expand_bits(unsigned v) {
    v &= 0x3FFu;
    v = (v | (v << 16)) & 0x030000FFu;
    v = (v | (v << 8))  & 0x0300F00Fu;
    v = (v | (v << 4))  & 0x030C30C3u;
    v = (v | (v << 2))  & 0x09249249u;
    return v;
}
__device__ __forceinline__ unsigned morton3(float x, float y, float z) {
    unsigned ix = min((unsigned)(x * (float)GRID_RES), (unsigned)(GRID_RES - 1));
    unsigned iy = min((unsigned)(y * (float)GRID_RES), (unsigned)(GRID_RES - 1));
    unsigned iz = min((unsigned)(z * (float)GRID_RES), (unsigned)(GRID_RES - 1));
    return (expand_bits(ix) << 2) | (expand_bits(iy) << 1) | expand_bits(iz);
}

// shared trilinear body: gathers 8 corners of level l and returns the
// interpolated float2 (bitwise-identical math to the reference path)
__device__ __forceinline__ float2 interp_level(
    const float* __restrict__ tables, const LvlParams& lp, int l,
    float cx, float cy, float cz)
{
    int ires = lp.r[l];
    float res = (float)ires;

    float sx = cx * res, sy = cy * res, sz = cz * res;
    float fx = floorf(sx), fy = floorf(sy), fz = floorf(sz);
    float wx = sx - fx, wy = sy - fy, wz = sz - fz;

    unsigned dx = (unsigned)ires;
    unsigned dy = lp.dy[l];
    unsigned dz = lp.dz[l];
    unsigned ux = (unsigned)((int)fx) * dx;
    unsigned uy = (unsigned)((int)fy) * dy;
    unsigned uz = (unsigned)((int)fz) * dz;

    const float2* __restrict__ tbl = (const float2*)tables + (size_t)l * TABLE_SIZE;

    float2 f000 = __ldg(tbl + ((ux      + uy      + uz     ) & HMASK));
    float2 f001 = __ldg(tbl + ((ux      + uy      + uz + dz) & HMASK));
    float2 f010 = __ldg(tbl + ((ux      + uy + dy + uz     ) & HMASK));
    float2 f011 = __ldg(tbl + ((ux      + uy + dy + uz + dz) & HMASK));
    float2 f100 = __ldg(tbl + ((ux + dx + uy      + uz     ) & HMASK));
    float2 f101 = __ldg(tbl + ((ux + dx + uy      + uz + dz) & HMASK));
    float2 f110 = __ldg(tbl + ((ux + dx + uy + dy + uz     ) & HMASK));
    float2 f111 = __ldg(tbl + ((ux + dx + uy + dy + uz + dz) & HMASK));

    float ex = 1.0f - wx, ey = 1.0f - wy, ez = 1.0f - wz;

    float c00a = f000.x * ex + f100.x * wx;
    float c00b = f000.y * ex + f100.y * wx;
    float c01a = f001.x * ex + f101.x * wx;
    float c01b = f001.y * ex + f101.y * wx;
    float c10a = f010.x * ex + f110.x * wx;
    float c10b = f010.y * ex + f110.y * wx;
    float c11a = f011.x * ex + f111.x * wx;
    float c11b = f011.y * ex + f111.y * wx;

    float c0a = c00a * ey + c10a * wy;
    float c0b = c00b * ey + c10b * wy;
    float c1a = c01a * ey + c11a * wy;
    float c1b = c01b * ey + c11b * wy;

    float2 r;
    r.x = c0a * ez + c1a * wz;
    r.y = c0b * ez + c1b * wz;
    return r;
}

// ---------------- hist (1 pt/thread) ----------------
__global__ void k_hist(const float* __restrict__ coords, int n) {
    int i = blockIdx.x * blockDim.x + threadIdx.x;
    if (i >= n) return;
    unsigned key = morton3(coords[3 * i], coords[3 * i + 1], coords[3 * i + 2]);
    atomicAdd(&g_hist[key], 1u);
}

// ---------------- fused block scan + (last block) top-level scan ----------------
__device__ __forceinline__ unsigned warp_incl_scan(unsigned v, int lane) {
    #pragma unroll
    for (int o = 1; o < 32; o <<= 1) {
        unsigned u = __shfl_up_sync(0xFFFFFFFFu, v, o);
        if (lane >= o) v += u;
    }
    return v;
}

__global__ __launch_bounds__(SCAN_BLOCK)
void k_scan_fused() {
    __shared__ unsigned warp_sums[16];
    __shared__ unsigned s_is_last;
    int t = threadIdx.x;
    int lane = t & 31, w = t >> 5;
    int gi = blockIdx.x * SCAN_BLOCK + t;

    unsigned v = g_hist[gi];
    unsigned inc = warp_incl_scan(v, lane);
    if (lane == 31) warp_sums[w] = inc;
    __syncthreads();
    if (w == 0) {
        unsigned ws = (lane < 16) ? warp_sums[lane] : 0u;
        ws = warp_incl_scan(ws, lane);
        if (lane < 16) warp_sums[lane] = ws;
    }
    __syncthreads();
    unsigned warp_off = (w > 0) ? warp_sums[w - 1] : 0u;
    g_hist[gi] = warp_off + inc - v;            // block-local exclusive
    if (t == SCAN_BLOCK - 1) g_blocksums[blockIdx.x] = warp_off + inc;

    __threadfence();
    __syncthreads();
    if (t == 0) {
        unsigned ticket = atomicAdd(&g_ticket, 1u);
        s_is_last = (ticket == NSCAN_BLOCKS - 1) ? 1u : 0u;
    }
    __syncthreads();
    if (s_is_last) {
        unsigned bv = g_blocksums[t];
        unsigned binc = warp_incl_scan(bv, lane);
        if (lane == 31) warp_sums[w] = binc;
        __syncthreads();
        if (w == 0) {
            unsigned ws = (lane < 16) ? warp_sums[lane] : 0u;
            ws = warp_incl_scan(ws, lane);
            if (lane < 16) warp_sums[lane] = ws;
        }
        __syncthreads();
        unsigned woff = (w > 0) ? warp_sums[w - 1] : 0u;
        g_blocksums[t] = woff + binc - bv;      // exclusive
        if (t == 0) g_ticket = 0;               // reset for next (graph) launch
        __threadfence();
    }
}

// ---------------- fused scatter + FINE levels (10..15, unsorted) ----------------
// Sorting gives no dedup at res>=161, so these levels run here on original
// points. The scatter's atomic/store latency hides under the 48 gathers.
__global__ __launch_bounds__(256)
void k_scatter_fine(const float* __restrict__ coords,
                    const float* __restrict__ tables,
                    float* __restrict__ out,
                    LvlParams lp, int n)
{
    __shared__ float s_fine[256][13];   // 12 used, +1 pad (bank-conflict-free)

    int t = threadIdx.x;
    int base = blockIdx.x * 256;
    int i = base + t;

    if (i < n) {
        float x = coords[3 * i], y = coords[3 * i + 1], z = coords[3 * i + 2];
        unsigned key = morton3(x, y, z);
        unsigned pos = atomicAdd(&g_hist[key], 1u) + __ldg(&g_blocksums[key >> 9]);
        g_pts[pos] = make_float4(x, y, z, __int_as_float(i));

        #pragma unroll 2
        for (int l = 10; l < NLV; ++l) {
            float2 r = interp_level(tables, lp, l, x, y, z);
            s_fine[t][2 * (l - 10)]     = r.x;
            s_fine[t][2 * (l - 10) + 1] = r.y;
        }
    }
    __syncthreads();

    // coalesced writeout of cols 20..31: 256 rows x 12 floats (48B/row, 1 line)
    #pragma unroll
    for (int it = 0; it < 12; ++it) {
        int idx = t + it * 256;
        int row = idx / 12, col = idx - row * 12;
        if (base + row < n)
            out[(size_t)(base + row) * 32 + 20 + col] = s_fine[row][col];
    }
}

// ---------------- coarse main (levels 0..9, sorted points) ----------------
// block = 160 threads = 5 warps, 32 points/tile; warp w handles the latency-
// balanced pair {w, 9-w}. Writes output cols 0..19.
__global__ __launch_bounds__(160)
void hashgrid_coarse(const float* __restrict__ tables,
                     float* __restrict__ out,
                     LvlParams lp, int n_points)
{
    __shared__ float s_out[32][21];

    int t = threadIdx.x;
    int w = t >> 5;          // warp 0..4
    int lane = t & 31;       // point within tile
    int base = blockIdx.x * 32;

    int pi = base + lane;
    float4 pt = make_float4(0.f, 0.f, 0.f, 0.f);
    if (pi < n_points) pt = __ldg(&g_pts[pi]);

    if (pi < n_points) {
        #pragma unroll
        for (int it = 0; it < 2; ++it) {
            int l = (it == 0) ? w : (9 - w);
            float2 r = interp_level(tables, lp, l, pt.x, pt.y, pt.z);
            s_out[lane][2 * l]     = r.x;
            s_out[lane][2 * l + 1] = r.y;
        }
    }
    __syncthreads();

    // coalesced writeout of cols 0..19: 32 rows x 20 floats (80B/row, 1 line)
    #pragma unroll
    for (int it = 0; it < 4; ++it) {
        int idx = t + it * 160;
        int row = idx / 20, col = idx - row * 20;
        int gp = __shfl_sync(0xFFFFFFFFu, __float_as_int(pt.w), row);
        if (base + row < n_points)
            out[(size_t)gp * 32 + col] = s_out[row][col];
    }
}

// ---------------- launch ----------------
extern "C" void kernel_launch(void* const* d_in, const int* in_sizes, int n_in,
                              void* d_out, int out_size)
{
    const float* coords = (const float*)d_in[0];
    const float* tables = (const float*)d_in[1];
    float* out = (float*)d_out;
    int n_points = in_sizes[0] / 3;

    LvlParams lp;
    double g = std::log(512.0 / 16.0) / 15.0;
    for (int l = 0; l < NLV; ++l) {
        int r = (int)std::floor(16.0 * std::exp((double)l * g));
        lp.r[l] = r;
        lp.dy[l] = (unsigned)r * P1;
        lp.dz[l] = (unsigned)r * P2;
    }

    void* hist_ptr = nullptr;
    cudaGetSymbolAddress(&hist_ptr, g_hist);
    cudaMemsetAsync(hist_ptr, 0, NBINS * sizeof(unsigned));

    int b = 256;
    int gpts = (n_points + b - 1) / b;
    k_hist<<<gpts, b>>>(coords, n_points);
    k_scan_fused<<<NSCAN_BLOCKS, SCAN_BLOCK>>>();
    k_scatter_fine<<<gpts, b>>>(coords, tables, out, lp, n_points);

    int ntiles = (n_points + 31) / 32;
    hashgrid_coarse<<<ntiles, 160>>>(tables, out, lp, n_points);
}

// round 17
// speedup vs baseline: 1.2097x; 1.2097x over previous
#include <cuda_runtime.h>
#include <cmath>

#define NLV 16
#define TABLE_SIZE (1u << 19)
#define HMASK (TABLE_SIZE - 1u)
#define P1 2654435761u
#define P2 805459861u

#define NP_MAX 1000000
#define GRID_BITS 6
#define GRID_RES (1 << GRID_BITS)          // 64
#define NBINS (1 << (3 * GRID_BITS))       // 262144
#define SCAN_BLOCK 512
#define NSCAN_BLOCKS (NBINS / SCAN_BLOCK)  // 512

struct LvlParams { int r[NLV]; unsigned dy[NLV]; unsigned dz[NLV]; };

// ---- scratch (static device globals; zero-initialized at load) ----
__device__ unsigned g_hist[NBINS];           // cleared by main kernel tail
__device__ unsigned g_blocksums[NSCAN_BLOCKS];
__device__ unsigned g_ticket = 0;            // self-cleaning: last block resets
__device__ float4   g_pts[NP_MAX];           // x,y,z, perm-as-bits

// ---------------- Morton ----------------
__device__ __forceinline__ unsigned expand_bits(unsigned v) {
    v &= 0x3FFu;
    v = (v | (v << 16)) & 0x030000FFu;
    v = (v | (v << 8))  & 0x0300F00Fu;
    v = (v | (v << 4))  & 0x030C30C3u;
    v = (v | (v << 2))  & 0x09249249u;
    return v;
}
__device__ __forceinline__ unsigned morton3(float x, float y, float z) {
    unsigned ix = min((unsigned)(x * (float)GRID_RES), (unsigned)(GRID_RES - 1));
    unsigned iy = min((unsigned)(y * (float)GRID_RES), (unsigned)(GRID_RES - 1));
    unsigned iz = min((unsigned)(z * (float)GRID_RES), (unsigned)(GRID_RES - 1));
    return (expand_bits(ix) << 2) | (expand_bits(iy) << 1) | expand_bits(iz);
}

// ---------------- hist (1 pt/thread — measured best) ----------------
__global__ void k_hist(const float* __restrict__ coords, int n) {
    int i = blockIdx.x * blockDim.x + threadIdx.x;
    if (i >= n) return;
    unsigned key = morton3(coords[3 * i], coords[3 * i + 1], coords[3 * i + 2]);
    atomicAdd(&g_hist[key], 1u);
}

// ---------------- fused block scan + (last block) top-level scan ----------------
__device__ __forceinline__ unsigned warp_incl_scan(unsigned v, int lane) {
    #pragma unroll
    for (int o = 1; o < 32; o <<= 1) {
        unsigned u = __shfl_up_sync(0xFFFFFFFFu, v, o);
        if (lane >= o) v += u;
    }
    return v;
}

__global__ __launch_bounds__(SCAN_BLOCK)
void k_scan_fused() {
    __shared__ unsigned warp_sums[16];
    __shared__ unsigned s_is_last;
    int t = threadIdx.x;
    int lane = t & 31, w = t >> 5;
    int gi = blockIdx.x * SCAN_BLOCK + t;

    // phase 1: block-local exclusive scan of g_hist, publish block sum
    unsigned v = g_hist[gi];
    unsigned inc = warp_incl_scan(v, lane);
    if (lane == 31) warp_sums[w] = inc;
    __syncthreads();
    if (w == 0) {
        unsigned ws = (lane < 16) ? warp_sums[lane] : 0u;
        ws = warp_incl_scan(ws, lane);
        if (lane < 16) warp_sums[lane] = ws;
    }
    __syncthreads();
    unsigned warp_off = (w > 0) ? warp_sums[w - 1] : 0u;
    g_hist[gi] = warp_off + inc - v;            // block-local exclusive
    if (t == SCAN_BLOCK - 1) g_blocksums[blockIdx.x] = warp_off + inc;

    // phase 2: last block to finish scans the 512 block sums
    __threadfence();
    __syncthreads();
    if (t == 0) {
        unsigned ticket = atomicAdd(&g_ticket, 1u);
        s_is_last = (ticket == NSCAN_BLOCKS - 1) ? 1u : 0u;
    }
    __syncthreads();
    if (s_is_last) {
        unsigned bv = g_blocksums[t];
        unsigned binc = warp_incl_scan(bv, lane);
        if (lane == 31) warp_sums[w] = binc;
        __syncthreads();
        if (w == 0) {
            unsigned ws = (lane < 16) ? warp_sums[lane] : 0u;
            ws = warp_incl_scan(ws, lane);
            if (lane < 16) warp_sums[lane] = ws;
        }
        __syncthreads();
        unsigned woff = (w > 0) ? warp_sums[w - 1] : 0u;
        g_blocksums[t] = woff + binc - bv;      // exclusive
        if (t == 0) g_ticket = 0;               // reset for next (graph) launch
        __threadfence();
    }
}

// ---------------- scatter (1 pt/thread; blocksum folded in) ----------------
__global__ void k_scatter(const float* __restrict__ coords, int n) {
    int i = blockIdx.x * blockDim.x + threadIdx.x;
    if (i >= n) return;
    float x = coords[3 * i], y = coords[3 * i + 1], z = coords[3 * i + 2];
    unsigned key = morton3(x, y, z);
    unsigned pos = atomicAdd(&g_hist[key], 1u) + __ldg(&g_blocksums[key >> 9]);
    g_pts[pos] = make_float4(x, y, z, __int_as_float(i));  // one STG.128
}

// ---------------- main kernel (R15 winner) ----------------
// block = 256 threads = 8 warps, 32 points/tile.
// Warp w processes level w (coarse, L1-resident) AND level 15-w (fine,
// L2-latency): pairing balances per-warp latency; x2 unroll gives up to 16
// outstanding gathers per warp. Each lane loads its own point's float4
// directly; ONE barrier before the transposed writeout.
// Also clears g_hist for the next graph replay (262144 entries across the
// first 262144 of 8M threads) — replaces the cudaMemsetAsync node.
__global__ __launch_bounds__(256)
void hashgrid_main(const float* __restrict__ tables,
                   float* __restrict__ out,
                   LvlParams lp, int n_points)
{
    __shared__ float s_out[32][33];

    int t = threadIdx.x;
    int w = t >> 5;          // warp 0..7
    int lane = t & 31;       // point within tile
    int base = blockIdx.x * 32;

    // restore g_hist = 0 invariant for the next launch
    int gid = blockIdx.x * 256 + t;
    if (gid < NBINS) g_hist[gid] = 0u;

    int pi = base + lane;
    float4 pt = make_float4(0.f, 0.f, 0.f, 0.f);
    if (pi < n_points) pt = __ldg(&g_pts[pi]);

    if (pi < n_points) {
        #pragma unroll
        for (int it = 0; it < 2; ++it) {
            int l = (it == 0) ? w : (NLV - 1 - w);
            int ires = lp.r[l];
            float res = (float)ires;

            float sx = pt.x * res, sy = pt.y * res, sz = pt.z * res;
            float fx = floorf(sx), fy = floorf(sy), fz = floorf(sz);
            float wx = sx - fx, wy = sy - fy, wz = sz - fz;

            // exact integer corner math; mod 2^19 via uint32 wrap
            unsigned dx = (unsigned)ires;
            unsigned dy = lp.dy[l];             // ires*P1 (host-precomputed)
            unsigned dz = lp.dz[l];             // ires*P2
            unsigned ux = (unsigned)((int)fx) * dx;
            unsigned uy = (unsigned)((int)fy) * dy;
            unsigned uz = (unsigned)((int)fz) * dz;

            const float2* __restrict__ tbl =
                (const float2*)tables + (size_t)l * TABLE_SIZE;

            float2 f000 = __ldg(tbl + ((ux      + uy      + uz     ) & HMASK));
            float2 f001 = __ldg(tbl + ((ux      + uy      + uz + dz) & HMASK));
            float2 f010 = __ldg(tbl + ((ux      + uy + dy + uz     ) & HMASK));
            float2 f011 = __ldg(tbl + ((ux      + uy + dy + uz + dz) & HMASK));
            float2 f100 = __ldg(tbl + ((ux + dx + uy      + uz     ) & HMASK));
            float2 f101 = __ldg(tbl + ((ux + dx + uy      + uz + dz) & HMASK));
            float2 f110 = __ldg(tbl + ((ux + dx + uy + dy + uz     ) & HMASK));
            float2 f111 = __ldg(tbl + ((ux + dx + uy + dy + uz + dz) & HMASK));

            float ex = 1.0f - wx, ey = 1.0f - wy, ez = 1.0f - wz;

            float c00a = f000.x * ex + f100.x * wx;
            float c00b = f000.y * ex + f100.y * wx;
            float c01a = f001.x * ex + f101.x * wx;
            float c01b = f001.y * ex + f101.y * wx;
            float c10a = f010.x * ex + f110.x * wx;
            float c10b = f010.y * ex + f110.y * wx;
            float c11a = f011.x * ex + f111.x * wx;
            float c11b = f011.y * ex + f111.y * wx;

            float c0a = c00a * ey + c10a * wy;
            float c0b = c00b * ey + c10b * wy;
            float c1a = c01a * ey + c11a * wy;
            float c1b = c01b * ey + c11b * wy;

            s_out[lane][2 * l]     = c0a * ez + c1a * wz;
            s_out[lane][2 * l + 1] = c0b * ez + c1b * wz;
        }
    }
    __syncthreads();

    // coalesced writeout: warp w writes rows 4w..4w+3 (128B contiguous each).
    // Every lane holds its own point's perm bits; fetch row's perm via shfl.
    #pragma unroll
    for (int it = 0; it < 4; ++it) {
        int row = w * 4 + it;
        int gp = __shfl_sync(0xFFFFFFFFu, __float_as_int(pt.w), row);
        if (base + row < n_points) {
            out[(size_t)gp * 32 + lane] = s_out[row][lane];
        }
    }
}

// ---------------- launch ----------------
extern "C" void kernel_launch(void* const* d_in, const int* in_sizes, int n_in,
                              void* d_out, int out_size)
{
    const float* coords = (const float*)d_in[0];
    const float* tables = (const float*)d_in[1];
    float* out = (float*)d_out;
    int n_points = in_sizes[0] / 3;

    LvlParams lp;
    double g = std::log(512.0 / 16.0) / 15.0;
    for (int l = 0; l < NLV; ++l) {
        int r = (int)std::floor(16.0 * std::exp((double)l * g));
        lp.r[l] = r;
        lp.dy[l] = (unsigned)r * P1;
        lp.dz[l] = (unsigned)r * P2;
    }

    int b = 256;
    int gpts = (n_points + b - 1) / b;
    k_hist<<<gpts, b>>>(coords, n_points);
    k_scan_fused<<<NSCAN_BLOCKS, SCAN_BLOCK>>>();
    k_scatter<<<gpts, b>>>(coords, n_points);

    int ntiles = (n_points + 31) / 32;
    hashgrid_main<<<ntiles, 256>>>(tables, out, lp, n_points);
}